// round 7
// baseline (speedup 1.0000x reference)
#include <cuda_runtime.h>
#include <cstdint>

namespace {

constexpr int kB = 64;
constexpr int kN = 8;
constexpr int kV = 128000;
constexpr int kCH = 32;                 // chunks per row (finer grid -> fills SMs)
constexpr int kQ4 = kV / kCH / 4;       // float4s per chunk = 1000
constexpr int kTPB = 128;
constexpr int kBonusBlocks = kB * kCH;        // 2048
constexpr int kGridTotal   = 2 * kB * kCH;    // 4096

__device__ float    g_bval[kB * kCH];
__device__ int      g_bidx[kB * kCH];
__device__ float    g_rval[kB * kCH];
__device__ int      g_ridx[kB * kCH];
__device__ unsigned g_ticket;

__device__ __forceinline__ float neg_inf() { return __int_as_float(0xff800000); }

// ---------------- JAX threefry2x32 (exact round structure) -------------------------
__device__ __forceinline__ void tfround(uint32_t& x0, uint32_t& x1, int r) {
  x0 += x1;
  x1 = __funnelshift_l(x1, x1, r);
  x1 ^= x0;
}

__device__ __forceinline__ uint2 threefry2x32(uint32_t k0, uint32_t k1,
                                              uint32_t x0, uint32_t x1) {
  uint32_t k2 = k0 ^ k1 ^ 0x1BD11BDAu;
  x0 += k0; x1 += k1;
  tfround(x0, x1, 13); tfround(x0, x1, 15); tfround(x0, x1, 26); tfround(x0, x1, 6);
  x0 += k1; x1 += k2 + 1u;
  tfround(x0, x1, 17); tfround(x0, x1, 29); tfround(x0, x1, 16); tfround(x0, x1, 24);
  x0 += k2; x1 += k0 + 2u;
  tfround(x0, x1, 13); tfround(x0, x1, 15); tfround(x0, x1, 26); tfround(x0, x1, 6);
  x0 += k0; x1 += k1 + 3u;
  tfround(x0, x1, 17); tfround(x0, x1, 29); tfround(x0, x1, 16); tfround(x0, x1, 24);
  x0 += k1; x1 += k2 + 4u;
  tfround(x0, x1, 13); tfround(x0, x1, 15); tfround(x0, x1, 26); tfround(x0, x1, 6);
  x0 += k2; x1 += k0 + 5u;
  return make_uint2(x0, x1);
}

__device__ __forceinline__ uint32_t rbits32(uint2 key, uint32_t idx) {
  uint2 o = threefry2x32(key.x, key.y, 0u, idx);
  return o.x ^ o.y;
}

__device__ __forceinline__ float uni01(uint32_t bits) {
  return __uint_as_float((bits >> 9) | 0x3f800000u) - 1.0f;
}

// t = -log(max(u, tiny)), accurate log (relative error matters for u near 1,
// which is exactly where argmax winners live).
__device__ __forceinline__ float tval(uint2 key, uint32_t idx) {
  float f = uni01(rbits32(key, idx));
  float u = fmaxf(f, 1.17549435e-38f);
  return -logf(u);
}

struct BestPair { float v; int i; };

// Pairwise tree over 4 candidates (index order c0<c1<c2<c3), then one strict
// compare vs running best. Strict '>' at each level keeps the lowest index on
// ties — identical semantics to the sequential first-index argmax.
__device__ __forceinline__ void upd4(BestPair& best, float v0, float v1, float v2,
                                     float v3, int i0) {
  float va = v0; int ia = i0;
  if (v1 > va) { va = v1; ia = i0 + 1; }
  float vb = v2; int ib = i0 + 2;
  if (v3 > vb) { vb = v3; ib = i0 + 3; }
  if (vb > va) { va = vb; ia = ib; }
  if (va > best.v) { best.v = va; best.i = ia; }
}

// Warp+block argmax (128 threads, tie-break min index), thread 0 holds result.
__device__ __forceinline__ BestPair block_argmax(BestPair best) {
  unsigned full = 0xffffffffu;
#pragma unroll
  for (int off = 16; off > 0; off >>= 1) {
    float ov = __shfl_down_sync(full, best.v, off);
    int   oi = __shfl_down_sync(full, best.i, off);
    if (ov > best.v || (ov == best.v && oi < best.i)) { best.v = ov; best.i = oi; }
  }
  __shared__ float sv[4];
  __shared__ int   si[4];
  int warp = threadIdx.x >> 5;
  int lane = threadIdx.x & 31;
  if (lane == 0) { sv[warp] = best.v; si[warp] = best.i; }
  __syncthreads();
  if (threadIdx.x == 0) {
#pragma unroll
    for (int w = 1; w < 4; w++) {
      if (sv[w] > best.v || (sv[w] == best.v && si[w] < best.i)) {
        best.v = sv[w]; best.i = si[w];
      }
    }
  }
  return best;
}

// accept decision for (b, n)
__device__ __forceinline__ bool accept_bn(int b, int n, const int* __restrict__ tok,
                                          const float* __restrict__ dp,
                                          const float* __restrict__ vp) {
  uint2 ku = threefry2x32(0u, 1u, 0u, 0u);   // split(key(1),3)[0] — const-folded
  int L = b * kN + n;
  float u = uni01(rbits32(ku, (uint32_t)L));
  int t = tok[L];
  t = min(max(t, 0), kV - 1);
  float q = dp[(size_t)L * kV + t];
  float p = vp[((size_t)b * (kN + 1) + n) * kV + t];
  return (u * q < p);
}

// ---------------- Single mega kernel ------------------------------------------------
// blocks [0, 2048):     bonus    (b = blk>>5, chunk = blk&31)
// blocks [2048, 4096):  recover  (self-computes em via lanes 0..7 ballot)
// Last block (ticket) combines partials, computes acc/em, writes all outputs.
__global__ void kGumbel(const int* __restrict__ tok, const float* __restrict__ dp,
                        const float* __restrict__ vp, float* __restrict__ out,
                        int out_size) {
  int blk = blockIdx.x;
  bool is_bonus = blk < kBonusBlocks;
  int rb = is_bonus ? blk : blk - kBonusBlocks;
  int b = rb / kCH;
  int c = rb % kCH;
  int t = threadIdx.x;

  BestPair best = {neg_inf(), 0x7fffffff};

  if (is_bonus) {
    uint2 kb = threefry2x32(0u, 1u, 0u, 2u);  // subkey 2 (const-folded)
    const float4* row = (const float4*)(vp + ((size_t)b * (kN + 1) + kN) * kV);
    uint32_t Lbase = (uint32_t)b * (uint32_t)kV;   // gumbel shape (B, V)
#pragma unroll 2
    for (int i = c * kQ4 + t; i < (c + 1) * kQ4; i += kTPB) {
      float4 p4 = row[i];
      int v = 4 * i;
      // maximize (p+eps)/t  ==  argmax log(p+eps) + G  (monotone)
      float v0 = __fdividef(p4.x + 1e-20f, tval(kb, Lbase + v + 0));
      float v1 = __fdividef(p4.y + 1e-20f, tval(kb, Lbase + v + 1));
      float v2 = __fdividef(p4.z + 1e-20f, tval(kb, Lbase + v + 2));
      float v3 = __fdividef(p4.w + 1e-20f, tval(kb, Lbase + v + 3));
      upd4(best, v0, v1, v2, v3, v);
    }
    best = block_argmax(best);
    if (t == 0) { g_bval[rb] = best.v; g_bidx[rb] = best.i; }
  } else {
    // self-compute em for batch b: lanes 0..7 of warp 0 + ballot
    __shared__ int s_em;
    if (t < 8) {
      bool acc = accept_bn(b, t, tok, dp, vp);
      unsigned m = __ballot_sync(0xffu, acc);
      if (t == 0) s_em = __ffs((~m) & 0x1FF) - 1;   // trailing-ones count, 8 if all
    }
    __syncthreads();
    int em = s_em;
    if (em < kN) {
      // argmax(log(r/S'+eps)+G) == argmax((r+eps)/t): /S' monotone, log monotone.
      uint2 kr = threefry2x32(0u, 1u, 0u, 1u);  // subkey 1 (const-folded)
      const float4* drow = (const float4*)(dp + ((size_t)b * kN + em) * kV);
      const float4* vrow = (const float4*)(vp + ((size_t)b * (kN + 1) + em) * kV);
      uint32_t Lbase = (uint32_t)(b * kN + em) * (uint32_t)kV;  // shape (B, N, V)
#pragma unroll 2
      for (int i = c * kQ4 + t; i < (c + 1) * kQ4; i += kTPB) {
        float4 d4 = drow[i];
        float4 v4 = vrow[i];
        int v = 4 * i;
        float v0 = __fdividef(fmaxf(v4.x - d4.x, 0.0f) + 1e-20f, tval(kr, Lbase + v + 0));
        float v1 = __fdividef(fmaxf(v4.y - d4.y, 0.0f) + 1e-20f, tval(kr, Lbase + v + 1));
        float v2 = __fdividef(fmaxf(v4.z - d4.z, 0.0f) + 1e-20f, tval(kr, Lbase + v + 2));
        float v3 = __fdividef(fmaxf(v4.w - d4.w, 0.0f) + 1e-20f, tval(kr, Lbase + v + 3));
        upd4(best, v0, v1, v2, v3, v);
      }
      best = block_argmax(best);
      if (t == 0) { g_rval[rb] = best.v; g_ridx[rb] = best.i; }
    }
  }

  // ---- deterministic last-block final assembly -----------------------------------
  __threadfence();
  __shared__ bool amLast;
  if (t == 0) {
    unsigned tk = atomicAdd(&g_ticket, 1u);
    amLast = (tk == (unsigned)(kGridTotal - 1));
  }
  __syncthreads();
  if (!amLast) return;
  if (t == 0) g_ticket = 0;           // reset for next graph replay
  __threadfence();

  int bb = t;
  if (bb < kB) {
    int acc = 0, em = 0;
    bool alive = true;
#pragma unroll
    for (int n = 0; n < kN; n++) {
      bool a = accept_bn(bb, n, tok, dp, vp);
      acc += a ? 1 : 0;
      if (alive) { if (a) em++; else alive = false; }
    }
    if (out_size >= kB * (kN + 1) + 2 * kB) {
      out[kB * (kN + 1) + bb] = (float)acc;
      out[kB * (kN + 1) + kB + bb] = (float)em;
    }

    volatile float* bval = g_bval;
    volatile int*   bidx = g_bidx;
    volatile float* rval = g_rval;
    volatile int*   ridx = g_ridx;
    float bv = neg_inf(); int bi = 0x7fffffff;
    for (int cc = 0; cc < kCH; cc++) {
      float v = bval[bb * kCH + cc]; int i = bidx[bb * kCH + cc];
      if (v > bv || (v == bv && i < bi)) { bv = v; bi = i; }
    }
    int fin = bi;
    if (em < kN) {
      float rv = neg_inf(); int ri = 0x7fffffff;
      for (int cc = 0; cc < kCH; cc++) {
        float v = rval[bb * kCH + cc]; int i = ridx[bb * kCH + cc];
        if (v > rv || (v == rv && i < ri)) { rv = v; ri = i; }
      }
      fin = ri;
    }
#pragma unroll
    for (int pos = 0; pos < kN + 1; pos++) {
      float o;
      if (pos < em)       o = (float)tok[bb * kN + pos];
      else if (pos == em) o = (float)fin;
      else                o = -1.0f;
      out[bb * (kN + 1) + pos] = o;
    }
  }
}

}  // namespace

extern "C" void kernel_launch(void* const* d_in, const int* in_sizes, int n_in,
                              void* d_out, int out_size) {
  const int*   tok = nullptr;
  const float* dp  = nullptr;
  const float* vp  = nullptr;
  for (int i = 0; i < n_in; i++) {
    if (in_sizes[i] == kB * kN)                      tok = (const int*)d_in[i];
    else if (in_sizes[i] == kB * kN * kV)            dp  = (const float*)d_in[i];
    else if (in_sizes[i] == kB * (kN + 1) * kV)      vp  = (const float*)d_in[i];
  }
  float* out = (float*)d_out;

  kGumbel<<<kGridTotal, kTPB>>>(tok, dp, vp, out, out_size);
}

// round 8
// speedup vs baseline: 1.1589x; 1.1589x over previous
#include <cuda_runtime.h>
#include <cstdint>

namespace {

constexpr int kB = 64;
constexpr int kN = 8;
constexpr int kV = 128000;
constexpr int kCH = 25;                 // chunks per row; kQ4 = 1280 = 5 * 2 * 128
constexpr int kQ4 = kV / kCH / 4;       // float4s per chunk = 1280
constexpr int kTPB = 128;
constexpr int kPairIters = kQ4 / (2 * kTPB);  // 5, exact
constexpr int kBonusBlocks = kB * kCH;        // 1600
constexpr int kGridTotal   = 2 * kB * kCH;    // 3200

__device__ float    g_bval[kB * kCH];
__device__ int      g_bidx[kB * kCH];
__device__ float    g_rval[kB * kCH];
__device__ int      g_ridx[kB * kCH];
__device__ unsigned g_ticket;

__device__ __forceinline__ float neg_inf() { return __int_as_float(0xff800000); }

// ---------------- JAX threefry2x32 (exact round structure) -------------------------
__device__ __forceinline__ void tfround(uint32_t& x0, uint32_t& x1, int r) {
  x0 += x1;
  x1 = __funnelshift_l(x1, x1, r);
  x1 ^= x0;
}

__device__ __forceinline__ uint2 threefry2x32(uint32_t k0, uint32_t k1,
                                              uint32_t x0, uint32_t x1) {
  uint32_t k2 = k0 ^ k1 ^ 0x1BD11BDAu;
  x0 += k0; x1 += k1;
  tfround(x0, x1, 13); tfround(x0, x1, 15); tfround(x0, x1, 26); tfround(x0, x1, 6);
  x0 += k1; x1 += k2 + 1u;
  tfround(x0, x1, 17); tfround(x0, x1, 29); tfround(x0, x1, 16); tfround(x0, x1, 24);
  x0 += k2; x1 += k0 + 2u;
  tfround(x0, x1, 13); tfround(x0, x1, 15); tfround(x0, x1, 26); tfround(x0, x1, 6);
  x0 += k0; x1 += k1 + 3u;
  tfround(x0, x1, 17); tfround(x0, x1, 29); tfround(x0, x1, 16); tfround(x0, x1, 24);
  x0 += k1; x1 += k2 + 4u;
  tfround(x0, x1, 13); tfround(x0, x1, 15); tfround(x0, x1, 26); tfround(x0, x1, 6);
  x0 += k2; x1 += k0 + 5u;
  return make_uint2(x0, x1);
}

__device__ __forceinline__ uint32_t rbits32(uint2 key, uint32_t idx) {
  uint2 o = threefry2x32(key.x, key.y, 0u, idx);
  return o.x ^ o.y;
}

__device__ __forceinline__ float uni01(uint32_t bits) {
  return __uint_as_float((bits >> 9) | 0x3f800000u) - 1.0f;
}

// t = -log(u), u = B-1 with B in [1,2). Dual path:
//   d = 2-B <= 0.125 (u >= 0.875, exact d): degree-6 Taylor of -log(1-d)/d,
//     rel err ~3e-7 — winners live here, relative accuracy preserved.
//   else: t = -__logf(u) >= 0.1335, abs err ~1.7e-7 -> rel err <= 1.3e-6.
// u==0 -> d=1 -> __logf path -> t=+inf -> val 0 (can never win a 128K argmax).
__device__ __forceinline__ float tval(uint2 key, uint32_t idx) {
  uint32_t bits = rbits32(key, idx);
  float B = __uint_as_float((bits >> 9) | 0x3f800000u);   // [1,2)
  float u = B - 1.0f;            // exact
  float d = 2.0f - B;            // exact (Sterbenz)
  float p = 0.14285714f;         // 1/7
  p = fmaf(p, d, 0.16666667f);   // 1/6
  p = fmaf(p, d, 0.2f);
  p = fmaf(p, d, 0.25f);
  p = fmaf(p, d, 0.33333333f);
  p = fmaf(p, d, 0.5f);
  p = fmaf(p, d, 1.0f);
  float ts = d * p;
  float tb = -__logf(u);
  return (d <= 0.125f) ? ts : tb;
}

struct BestPair { float v; int i; };

// Strict-'>' pairwise tree over 8 candidates: v[0..3] have indices iA+{0..3},
// v[4..7] have iB+{0..3}, with iA+3 < iB. Lowest index wins ties at every
// level (lower-index operand always on the left of a strict '>'), identical
// to the sequential first-index argmax.
__device__ __forceinline__ void upd8(BestPair& best, const float* v, int iA, int iB) {
  float a0 = v[0]; int j0 = iA;
  if (v[1] > a0) { a0 = v[1]; j0 = iA + 1; }
  float a1 = v[2]; int j1 = iA + 2;
  if (v[3] > a1) { a1 = v[3]; j1 = iA + 3; }
  float a2 = v[4]; int j2 = iB;
  if (v[5] > a2) { a2 = v[5]; j2 = iB + 1; }
  float a3 = v[6]; int j3 = iB + 2;
  if (v[7] > a3) { a3 = v[7]; j3 = iB + 3; }
  if (a1 > a0) { a0 = a1; j0 = j1; }
  if (a3 > a2) { a2 = a3; j2 = j3; }
  if (a2 > a0) { a0 = a2; j0 = j2; }
  if (a0 > best.v) { best.v = a0; best.i = j0; }
}

// Warp+block argmax (128 threads, tie-break min index), thread 0 holds result.
__device__ __forceinline__ BestPair block_argmax(BestPair best) {
  unsigned full = 0xffffffffu;
#pragma unroll
  for (int off = 16; off > 0; off >>= 1) {
    float ov = __shfl_down_sync(full, best.v, off);
    int   oi = __shfl_down_sync(full, best.i, off);
    if (ov > best.v || (ov == best.v && oi < best.i)) { best.v = ov; best.i = oi; }
  }
  __shared__ float sv[4];
  __shared__ int   si[4];
  int warp = threadIdx.x >> 5;
  int lane = threadIdx.x & 31;
  if (lane == 0) { sv[warp] = best.v; si[warp] = best.i; }
  __syncthreads();
  if (threadIdx.x == 0) {
#pragma unroll
    for (int w = 1; w < 4; w++) {
      if (sv[w] > best.v || (sv[w] == best.v && si[w] < best.i)) {
        best.v = sv[w]; best.i = si[w];
      }
    }
  }
  return best;
}

// accept decision for (b, n)
__device__ __forceinline__ bool accept_bn(int b, int n, const int* __restrict__ tok,
                                          const float* __restrict__ dp,
                                          const float* __restrict__ vp) {
  uint2 ku = threefry2x32(0u, 1u, 0u, 0u);   // split(key(1),3)[0] — const-folded
  int L = b * kN + n;
  float u = uni01(rbits32(ku, (uint32_t)L));
  int t = tok[L];
  t = min(max(t, 0), kV - 1);
  float q = dp[(size_t)L * kV + t];
  float p = vp[((size_t)b * (kN + 1) + n) * kV + t];
  return (u * q < p);
}

// ---------------- Single mega kernel ------------------------------------------------
__global__ void kGumbel(const int* __restrict__ tok, const float* __restrict__ dp,
                        const float* __restrict__ vp, float* __restrict__ out,
                        int out_size) {
  int blk = blockIdx.x;
  bool is_bonus = blk < kBonusBlocks;
  int rb = is_bonus ? blk : blk - kBonusBlocks;
  int b = rb / kCH;
  int c = rb % kCH;
  int t = threadIdx.x;

  BestPair best = {neg_inf(), 0x7fffffff};

  if (is_bonus) {
    uint2 kb = threefry2x32(0u, 1u, 0u, 2u);  // subkey 2 (const-folded)
    const float4* row = (const float4*)(vp + ((size_t)b * (kN + 1) + kN) * kV);
    uint32_t Lbase = (uint32_t)b * (uint32_t)kV;   // gumbel shape (B, V)
    int base = c * kQ4 + t;
#pragma unroll 1
    for (int k = 0; k < kPairIters; k++) {
      int i0 = base + k * 2 * kTPB;
      int i1 = i0 + kTPB;
      float4 pa = row[i0];
      float4 pb = row[i1];
      float vals[8];
      vals[0] = __fdividef(pa.x, tval(kb, Lbase + 4 * i0 + 0));
      vals[1] = __fdividef(pa.y, tval(kb, Lbase + 4 * i0 + 1));
      vals[2] = __fdividef(pa.z, tval(kb, Lbase + 4 * i0 + 2));
      vals[3] = __fdividef(pa.w, tval(kb, Lbase + 4 * i0 + 3));
      vals[4] = __fdividef(pb.x, tval(kb, Lbase + 4 * i1 + 0));
      vals[5] = __fdividef(pb.y, tval(kb, Lbase + 4 * i1 + 1));
      vals[6] = __fdividef(pb.z, tval(kb, Lbase + 4 * i1 + 2));
      vals[7] = __fdividef(pb.w, tval(kb, Lbase + 4 * i1 + 3));
      upd8(best, vals, 4 * i0, 4 * i1);
    }
    best = block_argmax(best);
    if (t == 0) { g_bval[rb] = best.v; g_bidx[rb] = best.i; }
  } else {
    __shared__ int s_em;
    if (t < 8) {
      bool acc = accept_bn(b, t, tok, dp, vp);
      unsigned m = __ballot_sync(0xffu, acc);
      if (t == 0) s_em = __ffs((~m) & 0x1FF) - 1;
    }
    __syncthreads();
    int em = s_em;
    if (em < kN) {
      uint2 kr = threefry2x32(0u, 1u, 0u, 1u);  // subkey 1 (const-folded)
      const float4* drow = (const float4*)(dp + ((size_t)b * kN + em) * kV);
      const float4* vrow = (const float4*)(vp + ((size_t)b * (kN + 1) + em) * kV);
      uint32_t Lbase = (uint32_t)(b * kN + em) * (uint32_t)kV;
      int base = c * kQ4 + t;
#pragma unroll 1
      for (int k = 0; k < kPairIters; k++) {
        int i0 = base + k * 2 * kTPB;
        int i1 = i0 + kTPB;
        float4 da = drow[i0];
        float4 va = vrow[i0];
        float4 db = drow[i1];
        float4 vb = vrow[i1];
        float vals[8];
        vals[0] = __fdividef(fmaxf(va.x - da.x, 0.0f), tval(kr, Lbase + 4 * i0 + 0));
        vals[1] = __fdividef(fmaxf(va.y - da.y, 0.0f), tval(kr, Lbase + 4 * i0 + 1));
        vals[2] = __fdividef(fmaxf(va.z - da.z, 0.0f), tval(kr, Lbase + 4 * i0 + 2));
        vals[3] = __fdividef(fmaxf(va.w - da.w, 0.0f), tval(kr, Lbase + 4 * i0 + 3));
        vals[4] = __fdividef(fmaxf(vb.x - db.x, 0.0f), tval(kr, Lbase + 4 * i1 + 0));
        vals[5] = __fdividef(fmaxf(vb.y - db.y, 0.0f), tval(kr, Lbase + 4 * i1 + 1));
        vals[6] = __fdividef(fmaxf(vb.z - db.z, 0.0f), tval(kr, Lbase + 4 * i1 + 2));
        vals[7] = __fdividef(fmaxf(vb.w - db.w, 0.0f), tval(kr, Lbase + 4 * i1 + 3));
        upd8(best, vals, 4 * i0, 4 * i1);
      }
      best = block_argmax(best);
      if (t == 0) { g_rval[rb] = best.v; g_ridx[rb] = best.i; }
    }
  }

  // ---- deterministic last-block final assembly -----------------------------------
  __threadfence();
  __shared__ bool amLast;
  if (t == 0) {
    unsigned tk = atomicAdd(&g_ticket, 1u);
    amLast = (tk == (unsigned)(kGridTotal - 1));
  }
  __syncthreads();
  if (!amLast) return;
  if (t == 0) g_ticket = 0;           // reset for next graph replay
  __threadfence();

  int bb = t;
  if (bb < kB) {
    int acc = 0, em = 0;
    bool alive = true;
#pragma unroll
    for (int n = 0; n < kN; n++) {
      bool a = accept_bn(bb, n, tok, dp, vp);
      acc += a ? 1 : 0;
      if (alive) { if (a) em++; else alive = false; }
    }
    if (out_size >= kB * (kN + 1) + 2 * kB) {
      out[kB * (kN + 1) + bb] = (float)acc;
      out[kB * (kN + 1) + kB + bb] = (float)em;
    }

    volatile float* bval = g_bval;
    volatile int*   bidx = g_bidx;
    volatile float* rval = g_rval;
    volatile int*   ridx = g_ridx;
    float bv = neg_inf(); int bi = 0x7fffffff;
    for (int cc = 0; cc < kCH; cc++) {
      float v = bval[bb * kCH + cc]; int i = bidx[bb * kCH + cc];
      if (v > bv || (v == bv && i < bi)) { bv = v; bi = i; }
    }
    int fin = bi;
    if (em < kN) {
      float rv = neg_inf(); int ri = 0x7fffffff;
      for (int cc = 0; cc < kCH; cc++) {
        float v = rval[bb * kCH + cc]; int i = ridx[bb * kCH + cc];
        if (v > rv || (v == rv && i < ri)) { rv = v; ri = i; }
      }
      fin = ri;
    }
#pragma unroll
    for (int pos = 0; pos < kN + 1; pos++) {
      float o;
      if (pos < em)       o = (float)tok[bb * kN + pos];
      else if (pos == em) o = (float)fin;
      else                o = -1.0f;
      out[bb * (kN + 1) + pos] = o;
    }
  }
}

}  // namespace

extern "C" void kernel_launch(void* const* d_in, const int* in_sizes, int n_in,
                              void* d_out, int out_size) {
  const int*   tok = nullptr;
  const float* dp  = nullptr;
  const float* vp  = nullptr;
  for (int i = 0; i < n_in; i++) {
    if (in_sizes[i] == kB * kN)                      tok = (const int*)d_in[i];
    else if (in_sizes[i] == kB * kN * kV)            dp  = (const float*)d_in[i];
    else if (in_sizes[i] == kB * (kN + 1) * kV)      vp  = (const float*)d_in[i];
  }
  float* out = (float*)d_out;

  kGumbel<<<kGridTotal, kTPB>>>(tok, dp, vp, out, out_size);
}